// round 8
// baseline (speedup 1.0000x reference)
#include <cuda_runtime.h>

typedef unsigned long long u64;
typedef unsigned int u32;

#define EPSV   1e-3f
#define ALPHAV 0.3f

#define Bn  16
#define Hn  64
#define Wn  64
#define Cn  1024
#define Gn  32
#define CGn 32
#define HT  16                    // rows per CTA (4 half-strips of 4 rows)
#define WT  64
#define HPOS (4 * WT)             // 256 positions per half-strip

#define DY_STRIDE 9               // padded stride (float4 units) -> conflict-free
#define DY_BUF_F4 (HPOS * DY_STRIDE)  // 2304 per buffer
#define PW_F4  256
#define SMEM_BYTES ((2 * DY_BUF_F4 + PW_F4) * 16 + 64 * 4)  // ~76.3 KB

__device__ __forceinline__ u64 ffma2(u64 a, u64 b, u64 c) {
    u64 d;
    asm("fma.rn.f32x2 %0, %1, %2, %3;" : "=l"(d) : "l"(a), "l"(b), "l"(c));
    return d;
}
__device__ __forceinline__ u64 pack2(float x, float y) {
    u64 d;
    asm("mov.b64 %0, {%1, %2};" : "=l"(d) : "f"(x), "f"(y));
    return d;
}
__device__ __forceinline__ float2 unpack2(u64 a) {
    float2 r;
    asm("mov.b64 {%0, %1}, %2;" : "=f"(r.x), "=f"(r.y) : "l"(a));
    return r;
}
__device__ __forceinline__ void cp16(u32 dst, const void* src) {
    asm volatile("cp.async.cg.shared.global [%0], [%1], 16;"
                 :: "r"(dst), "l"(src));
}

__global__ __launch_bounds__(256, 2)
void fused_gconv_kernel(const float* __restrict__ x,
                        const float* __restrict__ dwk,
                        const float* __restrict__ pwk,
                        const float* __restrict__ gamma,
                        const float* __restrict__ beta,
                        const float* __restrict__ mmean,
                        const float* __restrict__ mvar,
                        float* __restrict__ out)
{
    extern __shared__ float4 sm4[];
    float4* dyb0 = sm4;                     // dy ping buffer [256 pos][9] f4
    float4* dyb1 = sm4 + DY_BUF_F4;         // dy pong buffer
    float4* pw4  = sm4 + 2 * DY_BUF_F4;     // [32 c][8 d4] float4
    float*  sbs  = (float*)(pw4 + PW_F4);   // 32 floats scale
    float*  sbb  = sbs + 32;                // 32 floats bias

    const int g  = blockIdx.x;
    const int ht = blockIdx.y;
    const int b  = blockIdx.z;
    const int h0 = ht * HT;
    const int t  = threadIdx.x;
    const int c0 = g * CGn;

    // ---- async load: pointwise weights for this group (1024 floats) ----
    {
        const u32 pw_s = (u32)__cvta_generic_to_shared(pw4);
        cp16(pw_s + t * 16, pwk + g * CGn * CGn + t * 4);
        asm volatile("cp.async.commit_group;");
    }

    // ---- BN scale/bias (consumer-side threads) ----
    if (t < 32) {
        const int c = c0 + t;
        const float s = gamma[c] * rsqrtf(mvar[c] + EPSV);
        sbs[t] = s;
        sbb[t] = beta[c] - mmean[c] * s;
    }

    // Producers = warps 4..7 (hi-wid -> arbiter priority for LDG issue).
    const bool producer = (t >= 128);

    // ---- producer state ----
    const int pt = t & 127;
    const int c2 = pt & 15;          // channel pair
    const int wq = pt >> 4;          // 0..7 -> 8 cols each
    const float* xb = x + (u64)b * Hn * Wn * Cn + c0 + c2 * 2;
    u64 kreg[9];
    if (producer) {
        #pragma unroll
        for (int tap = 0; tap < 9; tap++)
            kreg[tap] = *(const u64*)(dwk + tap * Cn + c0 + c2 * 2);
    }

    // depthwise for half-strip s (4 rows x 64 w): 4r x 8c x 2ch per thread
    auto dw_half = [&](int s, float4* buf) {
        const int hbase = h0 + s * 4 - 1;
        const int wbase = wq * 8 - 1;
        u64 acc[4][8];
        #pragma unroll
        for (int i = 0; i < 4; i++)
            #pragma unroll
            for (int j = 0; j < 8; j++) acc[i][j] = 0ull;

        #pragma unroll
        for (int ci = 0; ci < 10; ci++) {
            const int w = wbase + ci;
            const bool wok = (unsigned)w < (unsigned)Wn;
            u64 col[6];
            #pragma unroll
            for (int rr = 0; rr < 6; rr++) {
                const int h = hbase + rr;
                col[rr] = (wok && (unsigned)h < (unsigned)Hn)
                          ? *(const u64*)(xb + ((long)h * Wn + w) * Cn) : 0ull;
            }
            #pragma unroll
            for (int kw = 0; kw < 3; kw++) {
                const int oc = ci - kw;
                if (oc >= 0 && oc < 8) {
                    #pragma unroll
                    for (int kr = 0; kr < 3; kr++) {
                        #pragma unroll
                        for (int orow = 0; orow < 4; orow++)
                            acc[orow][oc] =
                                ffma2(col[orow + kr], kreg[kr * 3 + kw], acc[orow][oc]);
                    }
                }
            }
        }
        char* dyb = (char*)buf;
        #pragma unroll
        for (int orow = 0; orow < 4; orow++) {
            #pragma unroll
            for (int oc = 0; oc < 8; oc++) {
                const int pos = orow * WT + wq * 8 + oc;   // local 0..255
                *(u64*)(dyb + pos * (DY_STRIDE * 16) + c2 * 8) = acc[orow][oc];
            }
        }
    };

    // pointwise + BN + LeakyReLU for half-strip s: 8 pos x 8 d per thread
    auto pw_half = [&](int s, const float4* buf) {
        const int dgroup = t & 3;
        const int d0 = dgroup * 8;
        const int posset = (t >> 2) & 31;        // 0..31; positions posset+32*i

        u64 acc[8][4];
        #pragma unroll
        for (int i = 0; i < 8; i++)
            #pragma unroll
            for (int j = 0; j < 4; j++) acc[i][j] = 0ull;

        #pragma unroll
        for (int cq = 0; cq < 8; cq++) {
            float4 dyv[8];
            #pragma unroll
            for (int i = 0; i < 8; i++)
                dyv[i] = buf[(posset + 32 * i) * DY_STRIDE + cq];
            #pragma unroll
            for (int cc = 0; cc < 4; cc++) {
                const int c = cq * 4 + cc;
                const ulonglong2 pa = *(const ulonglong2*)&pw4[c * 8 + dgroup * 2];
                const ulonglong2 pb = *(const ulonglong2*)&pw4[c * 8 + dgroup * 2 + 1];
                #pragma unroll
                for (int i = 0; i < 8; i++) {
                    const float dc = ((const float*)&dyv[i])[cc];
                    const u64 dp = pack2(dc, dc);
                    acc[i][0] = ffma2(dp, pa.x, acc[i][0]);
                    acc[i][1] = ffma2(dp, pa.y, acc[i][1]);
                    acc[i][2] = ffma2(dp, pb.x, acc[i][2]);
                    acc[i][3] = ffma2(dp, pb.y, acc[i][3]);
                }
            }
        }

        const ulonglong2 S0  = *(const ulonglong2*)&sbs[d0];
        const ulonglong2 S1  = *(const ulonglong2*)&sbs[d0 + 4];
        const ulonglong2 Bb0 = *(const ulonglong2*)&sbb[d0];
        const ulonglong2 Bb1 = *(const ulonglong2*)&sbb[d0 + 4];
        #pragma unroll
        for (int i = 0; i < 8; i++) {
            const int p = posset + 32 * i;
            const int row = p >> 6, wloc = p & 63;
            const u64 y0 = ffma2(acc[i][0], S0.x, Bb0.x);
            const u64 y1 = ffma2(acc[i][1], S0.y, Bb0.y);
            const u64 y2 = ffma2(acc[i][2], S1.x, Bb1.x);
            const u64 y3 = ffma2(acc[i][3], S1.y, Bb1.y);
            const float2 f0 = unpack2(y0), f1 = unpack2(y1);
            const float2 f2 = unpack2(y2), f3 = unpack2(y3);
            float r[8] = {f0.x, f0.y, f1.x, f1.y, f2.x, f2.y, f3.x, f3.y};
            #pragma unroll
            for (int k = 0; k < 8; k++)
                r[k] = fmaxf(r[k], 0.f) + ALPHAV * fminf(r[k], 0.f);
            float* op = out + (((u64)b * Hn + h0 + s * 4 + row) * Wn + wloc) * Cn + c0 + d0;
            *(float4*)op       = make_float4(r[0], r[1], r[2], r[3]);
            *(float4*)(op + 4) = make_float4(r[4], r[5], r[6], r[7]);
        }
    };

    // ---- 4-half pipeline with ping-pong dy buffers ----
    // dw(0) | dw(1)+pw(0) | dw(2)+pw(1) | dw(3)+pw(2) | pw(3)
    if (producer) dw_half(0, dyb0);

    asm volatile("cp.async.wait_group 0;" ::: "memory");
    __syncthreads();                    // dy(0) ready; weights ready

    if (producer) dw_half(1, dyb1);
    else          pw_half(0, dyb0);
    __syncthreads();

    if (producer) dw_half(2, dyb0);
    else          pw_half(1, dyb1);
    __syncthreads();

    if (producer) dw_half(3, dyb1);
    else          pw_half(2, dyb0);
    __syncthreads();

    if (!producer) pw_half(3, dyb1);
}

extern "C" void kernel_launch(void* const* d_in, const int* in_sizes, int n_in,
                              void* d_out, int out_size)
{
    const float* x     = (const float*)d_in[0];
    const float* dwk   = (const float*)d_in[1];
    const float* pwk   = (const float*)d_in[2];
    const float* gam   = (const float*)d_in[3];
    const float* bet   = (const float*)d_in[4];
    const float* mmean = (const float*)d_in[5];
    const float* mvar  = (const float*)d_in[6];
    float* out = (float*)d_out;

    cudaFuncSetAttribute(fused_gconv_kernel,
                         cudaFuncAttributeMaxDynamicSharedMemorySize, SMEM_BYTES);

    dim3 grid(Gn, Hn / HT, Bn);   // 32 x 4 x 16 = 2048 blocks
    fused_gconv_kernel<<<grid, 256, SMEM_BYTES>>>(x, dwk, pwk, gam, bet, mmean, mvar, out);
}

// round 10
// speedup vs baseline: 1.0194x; 1.0194x over previous
#include <cuda_runtime.h>

typedef unsigned long long u64;
typedef unsigned int u32;

#define EPSV   1e-3f
#define ALPHAV 0.3f

#define Bn  16
#define Hn  64
#define Wn  64
#define Cn  1024
#define Gn  32
#define CGn 32
#define HT  8
#define WT  32
#define NPOS (HT * WT)            // 256 positions per tile

#define DY_STRIDE 9               // padded stride (float4 units) -> conflict-free
#define DY_F4  (NPOS * DY_STRIDE) // 2304
#define PW_F4  256
#define ROWF4  272                // 34 w * 8 c4 (float4 units per tile row)
#define SX_F4  (10 * ROWF4)       // 2720
#define SMEM_BYTES ((DY_F4 + PW_F4 + SX_F4) * 16 + 64 * 4)  // ~84.7 KB

__device__ __forceinline__ u64 ffma2(u64 a, u64 b, u64 c) {
    u64 d;
    asm("fma.rn.f32x2 %0, %1, %2, %3;" : "=l"(d) : "l"(a), "l"(b), "l"(c));
    return d;
}
__device__ __forceinline__ u64 pack2(float x, float y) {
    u64 d;
    asm("mov.b64 %0, {%1, %2};" : "=l"(d) : "f"(x), "f"(y));
    return d;
}
__device__ __forceinline__ float2 unpack2(u64 a) {
    float2 r;
    asm("mov.b64 {%0, %1}, %2;" : "=f"(r.x), "=f"(r.y) : "l"(a));
    return r;
}
__device__ __forceinline__ void cp16(u32 dst, const void* src, int sz) {
    asm volatile("cp.async.cg.shared.global [%0], [%1], 16, %2;"
                 :: "r"(dst), "l"(src), "r"(sz));
}
__device__ __forceinline__ u64 lds64(u32 addr) {
    u64 v;
    asm volatile("ld.shared.b64 %0, [%1];" : "=l"(v) : "r"(addr));
    return v;
}
__device__ __forceinline__ void sts64(u32 addr, u64 v) {
    asm volatile("st.shared.b64 [%0], %1;" :: "r"(addr), "l"(v));
}

__global__ __launch_bounds__(256, 2)
void fused_gconv_kernel(const float* __restrict__ x,
                        const float* __restrict__ dwk,
                        const float* __restrict__ pwk,
                        const float* __restrict__ gamma,
                        const float* __restrict__ beta,
                        const float* __restrict__ mmean,
                        const float* __restrict__ mvar,
                        float* __restrict__ out)
{
    extern __shared__ float4 sm4[];
    float4* dy4 = sm4;                      // [256 pos][9] float4 (8 used + 1 pad)
    float4* pw4 = dy4 + DY_F4;              // [32 c][8 d4] float4
    float4* sx4 = pw4 + PW_F4;              // [10 rows][34 w][8 c4] float4
    float*  sbs = (float*)(sx4 + SX_F4);    // 32 floats scale
    float*  sbb = sbs + 32;                 // 32 floats bias

    const int g  = blockIdx.x;
    const int ht = blockIdx.y >> 1;
    const int wt = blockIdx.y & 1;
    const int b  = blockIdx.z;
    const int h0 = ht * HT;
    const int w0 = wt * WT;
    const int t  = threadIdx.x;
    const int c0 = g * CGn;

    const u32 sx_s = (u32)__cvta_generic_to_shared(sx4);
    const u32 pw_s = (u32)__cvta_generic_to_shared(pw4);
    const u32 dy_s = (u32)__cvta_generic_to_shared(dy4);

    // ---- async stage: pw weights + x tile [10][34][32] with zero halo ----
    cp16(pw_s + t * 16, pwk + g * CGn * CGn + t * 4, 16);
    {
        const float* xb = x + (u64)b * Hn * Wn * Cn;
        #pragma unroll
        for (int k = 0; k < 11; k++) {
            const int i = t + k * 256;
            if (i < SX_F4) {
                const int row = i / ROWF4;
                const int rem = i - row * ROWF4;
                const int w34 = rem >> 3;
                const int cc4 = rem & 7;
                const int h  = h0 - 1 + row;
                const int wg = w0 - 1 + w34;
                const bool ok = ((unsigned)h < (unsigned)Hn) &&
                                ((unsigned)wg < (unsigned)Wn);
                const float* src = ok ? (xb + ((u64)h * Wn + wg) * Cn + c0 + cc4 * 4) : xb;
                cp16(sx_s + i * 16, src, ok ? 16 : 0);
            }
        }
    }
    asm volatile("cp.async.commit_group;");

    // ---- BN scale/bias + dw taps (regular loads, overlap with cp.async) ----
    if (t < 32) {
        const int c = c0 + t;
        const float s = gamma[c] * rsqrtf(mvar[c] + EPSV);
        sbs[t] = s;
        sbb[t] = beta[c] - mmean[c] * s;
    }
    const int c2 = t & 15;           // channel pair
    u64 kreg[9];
    #pragma unroll
    for (int tap = 0; tap < 9; tap++)
        kreg[tap] = *(const u64*)(dwk + tap * Cn + c0 + c2 * 2);

    asm volatile("cp.async.wait_group 0;" ::: "memory");
    __syncthreads();

    // ---- depthwise 3x3 from smem tile: 4 rows x 4 cols x 2 ch per thread ----
    {
        const int wq = (t >> 4) & 7;     // 8 col-quads -> 32 w
        const int rb = t >> 7;           // 0/1 -> rows rb*4..rb*4+3

        u64 acc[4][4];
        #pragma unroll
        for (int i = 0; i < 4; i++)
            #pragma unroll
            for (int j = 0; j < 4; j++) acc[i][j] = 0ull;

        #pragma unroll
        for (int ci = 0; ci < 6; ci++) {
            const int tw = wq * 4 + ci;      // tile w index (tile w0 = global w0-1)
            u64 col[6];
            #pragma unroll
            for (int rr = 0; rr < 6; rr++)
                col[rr] = lds64(sx_s + ((rb * 4 + rr) * 34 + tw) * 128 + c2 * 8);
            #pragma unroll
            for (int kw = 0; kw < 3; kw++) {
                const int oc = ci - kw;
                if (oc >= 0 && oc < 4) {
                    #pragma unroll
                    for (int kr = 0; kr < 3; kr++) {
                        #pragma unroll
                        for (int orow = 0; orow < 4; orow++)
                            acc[orow][oc] =
                                ffma2(col[orow + kr], kreg[kr * 3 + kw], acc[orow][oc]);
                    }
                }
            }
        }
        #pragma unroll
        for (int orow = 0; orow < 4; orow++) {
            #pragma unroll
            for (int oc = 0; oc < 4; oc++) {
                const int pos = (rb * 4 + orow) * WT + wq * 4 + oc;
                sts64(dy_s + pos * (DY_STRIDE * 16) + c2 * 8, acc[orow][oc]);
            }
        }
    }
    __syncthreads();

    // ---- pointwise 32x32 per group + BN + LeakyReLU (8 pos x 4 d / thread) ----
    const int dgroup = t & 7;        // which 4 output channels
    const int d0 = dgroup * 4;
    const int posset = t >> 3;       // 0..31; positions posset + 32*i, i=0..7

    u64 acc[8][2];
    #pragma unroll
    for (int i = 0; i < 8; i++) { acc[i][0] = 0ull; acc[i][1] = 0ull; }

    #pragma unroll
    for (int cq = 0; cq < 8; cq++) {
        float4 dyv[8];
        #pragma unroll
        for (int i = 0; i < 8; i++)
            dyv[i] = dy4[(posset + 32 * i) * DY_STRIDE + cq];
        #pragma unroll
        for (int cc = 0; cc < 4; cc++) {
            const int c = cq * 4 + cc;
            const ulonglong2 pa = *(const ulonglong2*)&pw4[c * 8 + dgroup];
            #pragma unroll
            for (int i = 0; i < 8; i++) {
                const float dc = ((const float*)&dyv[i])[cc];
                const u64 dp = pack2(dc, dc);
                acc[i][0] = ffma2(dp, pa.x, acc[i][0]);
                acc[i][1] = ffma2(dp, pa.y, acc[i][1]);
            }
        }
    }

    // epilogue: BN (one FFMA2 per pair) + LeakyReLU + float4 stores
    const ulonglong2 S  = *(const ulonglong2*)&sbs[d0];
    const ulonglong2 Bb = *(const ulonglong2*)&sbb[d0];
    #pragma unroll
    for (int i = 0; i < 8; i++) {
        const int p = posset + 32 * i;
        const int row = p >> 5, wloc = p & 31;
        const u64 y0 = ffma2(acc[i][0], S.x, Bb.x);
        const u64 y1 = ffma2(acc[i][1], S.y, Bb.y);
        const float2 f0 = unpack2(y0), f1 = unpack2(y1);
        float r[4] = {f0.x, f0.y, f1.x, f1.y};
        #pragma unroll
        for (int k = 0; k < 4; k++)
            r[k] = fmaxf(r[k], 0.f) + ALPHAV * fminf(r[k], 0.f);
        float* op = out + (((u64)b * Hn + h0 + row) * Wn + w0 + wloc) * Cn + c0 + d0;
        *(float4*)op = make_float4(r[0], r[1], r[2], r[3]);
    }
}

extern "C" void kernel_launch(void* const* d_in, const int* in_sizes, int n_in,
                              void* d_out, int out_size)
{
    const float* x     = (const float*)d_in[0];
    const float* dwk   = (const float*)d_in[1];
    const float* pwk   = (const float*)d_in[2];
    const float* gam   = (const float*)d_in[3];
    const float* bet   = (const float*)d_in[4];
    const float* mmean = (const float*)d_in[5];
    const float* mvar  = (const float*)d_in[6];
    float* out = (float*)d_out;

    cudaFuncSetAttribute(fused_gconv_kernel,
                         cudaFuncAttributeMaxDynamicSharedMemorySize, SMEM_BYTES);

    dim3 grid(Gn, (Hn / HT) * (Wn / WT), Bn);   // 32 x 16 x 16 = 8192 blocks
    fused_gconv_kernel<<<grid, 256, SMEM_BYTES>>>(x, dwk, pwk, gam, bet, mmean, mvar, out);
}

// round 11
// speedup vs baseline: 1.0885x; 1.0678x over previous
#include <cuda_runtime.h>

typedef unsigned long long u64;
typedef unsigned int u32;

#define EPSV   1e-3f
#define ALPHAV 0.3f

#define Bn  16
#define Hn  64
#define Wn  64
#define Cn  1024
#define Gn  32
#define CGn 32
#define HT  8
#define WT  32

#define DY_STRIDE 9                // padded stride (float4 units) -> conflict-free
#define DY_F4  (128 * DY_STRIDE)   // half-strip dy: 128 pos x 9 f4 = 1152
#define PW_F4  256
#define ROWF4  272                 // 34 w * 8 c4 (float4 units per tile row)
#define SX_F4  (10 * ROWF4)        // 2720
#define SMEM_BYTES ((DY_F4 + PW_F4 + SX_F4) * 16 + 64 * 4)  // ~64.8 KB -> 3 CTAs/SM

__device__ __forceinline__ u64 ffma2(u64 a, u64 b, u64 c) {
    u64 d;
    asm("fma.rn.f32x2 %0, %1, %2, %3;" : "=l"(d) : "l"(a), "l"(b), "l"(c));
    return d;
}
__device__ __forceinline__ u64 pack2(float x, float y) {
    u64 d;
    asm("mov.b64 %0, {%1, %2};" : "=l"(d) : "f"(x), "f"(y));
    return d;
}
__device__ __forceinline__ float2 unpack2(u64 a) {
    float2 r;
    asm("mov.b64 {%0, %1}, %2;" : "=f"(r.x), "=f"(r.y) : "l"(a));
    return r;
}
__device__ __forceinline__ void cp16(u32 dst, const void* src, int sz) {
    asm volatile("cp.async.cg.shared.global [%0], [%1], 16, %2;"
                 :: "r"(dst), "l"(src), "r"(sz));
}
__device__ __forceinline__ u64 lds64(u32 addr) {
    u64 v;
    asm volatile("ld.shared.b64 %0, [%1];" : "=l"(v) : "r"(addr));
    return v;
}
__device__ __forceinline__ void sts64(u32 addr, u64 v) {
    asm volatile("st.shared.b64 [%0], %1;" :: "r"(addr), "l"(v));
}

__global__ __launch_bounds__(256, 3)
void fused_gconv_kernel(const float* __restrict__ x,
                        const float* __restrict__ dwk,
                        const float* __restrict__ pwk,
                        const float* __restrict__ gamma,
                        const float* __restrict__ beta,
                        const float* __restrict__ mmean,
                        const float* __restrict__ mvar,
                        float* __restrict__ out)
{
    extern __shared__ float4 sm4[];
    float4* dy4 = sm4;                      // [128 pos][9] float4 (half strip)
    float4* pw4 = dy4 + DY_F4;              // [32 c][8 d4] float4
    float4* sx4 = pw4 + PW_F4;              // [10 rows][34 w][8 c4] float4
    float*  sbs = (float*)(sx4 + SX_F4);    // 32 floats scale
    float*  sbb = sbs + 32;                 // 32 floats bias

    const int g  = blockIdx.x;
    const int ht = blockIdx.y >> 1;
    const int wt = blockIdx.y & 1;
    const int b  = blockIdx.z;
    const int h0 = ht * HT;
    const int w0 = wt * WT;
    const int t  = threadIdx.x;
    const int c0 = g * CGn;

    const u32 sx_s = (u32)__cvta_generic_to_shared(sx4);
    const u32 pw_s = (u32)__cvta_generic_to_shared(pw4);
    const u32 dy_s = (u32)__cvta_generic_to_shared(dy4);

    // ---- async stage: pw weights + full x tile [10][34][32] with zero halo ----
    cp16(pw_s + t * 16, pwk + g * CGn * CGn + t * 4, 16);
    {
        const float* xb = x + (u64)b * Hn * Wn * Cn;
        #pragma unroll
        for (int k = 0; k < 11; k++) {
            const int i = t + k * 256;
            if (i < SX_F4) {
                const int row = i / ROWF4;
                const int rem = i - row * ROWF4;
                const int w34 = rem >> 3;
                const int cc4 = rem & 7;
                const int h  = h0 - 1 + row;
                const int wg = w0 - 1 + w34;
                const bool ok = ((unsigned)h < (unsigned)Hn) &&
                                ((unsigned)wg < (unsigned)Wn);
                const float* src = ok ? (xb + ((u64)h * Wn + wg) * Cn + c0 + cc4 * 4) : xb;
                cp16(sx_s + i * 16, src, ok ? 16 : 0);
            }
        }
    }
    asm volatile("cp.async.commit_group;");

    // ---- BN scale/bias + dw taps (regular loads, overlap with cp.async) ----
    if (t < 32) {
        const int c = c0 + t;
        const float s = gamma[c] * rsqrtf(mvar[c] + EPSV);
        sbs[t] = s;
        sbb[t] = beta[c] - mmean[c] * s;
    }
    const int c2 = t & 15;           // channel pair
    u64 kreg[9];
    #pragma unroll
    for (int tap = 0; tap < 9; tap++)
        kreg[tap] = *(const u64*)(dwk + tap * Cn + c0 + c2 * 2);

    // ---- per-thread mappings ----
    const int wq = (t >> 4) & 7;     // dw: 8 col-quads -> 32 w
    const int rh = t >> 7;           // dw: 0/1 -> rows rh*2..rh*2+1 of the half
    const int dgroup = t & 7;        // pw: which 4 output channels
    const int d0 = dgroup * 4;
    const int posset = t >> 3;       // pw: 0..31; positions posset + 32*i, i=0..3

    // depthwise for half h (4 rows x 32 w): 2r x 4c x 2ch per thread
    auto dw_half = [&](int h) {
        u64 acc[2][4];
        #pragma unroll
        for (int i = 0; i < 2; i++)
            #pragma unroll
            for (int j = 0; j < 4; j++) acc[i][j] = 0ull;

        const int trow0 = h * 4 + rh * 2;   // first tile row of 4-row window
        #pragma unroll
        for (int ci = 0; ci < 6; ci++) {
            const int tw = wq * 4 + ci;     // tile w (tile col 0 = global w0-1)
            u64 col[4];
            #pragma unroll
            for (int rr = 0; rr < 4; rr++)
                col[rr] = lds64(sx_s + ((trow0 + rr) * 34 + tw) * 128 + c2 * 8);
            #pragma unroll
            for (int kw = 0; kw < 3; kw++) {
                const int oc = ci - kw;
                if (oc >= 0 && oc < 4) {
                    #pragma unroll
                    for (int kr = 0; kr < 3; kr++) {
                        #pragma unroll
                        for (int orow = 0; orow < 2; orow++)
                            acc[orow][oc] =
                                ffma2(col[orow + kr], kreg[kr * 3 + kw], acc[orow][oc]);
                    }
                }
            }
        }
        #pragma unroll
        for (int orow = 0; orow < 2; orow++) {
            #pragma unroll
            for (int oc = 0; oc < 4; oc++) {
                const int pos = (rh * 2 + orow) * WT + wq * 4 + oc;   // 0..127
                sts64(dy_s + pos * (DY_STRIDE * 16) + c2 * 8, acc[orow][oc]);
            }
        }
    };

    // pointwise + BN + LeakyReLU for half h: 4 pos x 4 d per thread
    auto pw_half = [&](int h) {
        u64 acc[4][2];
        #pragma unroll
        for (int i = 0; i < 4; i++) { acc[i][0] = 0ull; acc[i][1] = 0ull; }

        #pragma unroll
        for (int cq = 0; cq < 8; cq++) {
            float4 dyv[4];
            #pragma unroll
            for (int i = 0; i < 4; i++)
                dyv[i] = dy4[(posset + 32 * i) * DY_STRIDE + cq];
            #pragma unroll
            for (int cc = 0; cc < 4; cc++) {
                const int c = cq * 4 + cc;
                const ulonglong2 pa = *(const ulonglong2*)&pw4[c * 8 + dgroup];
                #pragma unroll
                for (int i = 0; i < 4; i++) {
                    const float dc = ((const float*)&dyv[i])[cc];
                    const u64 dp = pack2(dc, dc);
                    acc[i][0] = ffma2(dp, pa.x, acc[i][0]);
                    acc[i][1] = ffma2(dp, pa.y, acc[i][1]);
                }
            }
        }

        const ulonglong2 S  = *(const ulonglong2*)&sbs[d0];
        const ulonglong2 Bb = *(const ulonglong2*)&sbb[d0];
        #pragma unroll
        for (int i = 0; i < 4; i++) {
            const int p = posset + 32 * i;          // 0..127
            const int row = p >> 5, wloc = p & 31;
            const u64 y0 = ffma2(acc[i][0], S.x, Bb.x);
            const u64 y1 = ffma2(acc[i][1], S.y, Bb.y);
            const float2 f0 = unpack2(y0), f1 = unpack2(y1);
            float r[4] = {f0.x, f0.y, f1.x, f1.y};
            #pragma unroll
            for (int k = 0; k < 4; k++)
                r[k] = fmaxf(r[k], 0.f) + ALPHAV * fminf(r[k], 0.f);
            float* op = out + (((u64)b * Hn + h0 + h * 4 + row) * Wn + w0 + wloc) * Cn
                            + c0 + d0;
            *(float4*)op = make_float4(r[0], r[1], r[2], r[3]);
        }
    };

    asm volatile("cp.async.wait_group 0;" ::: "memory");
    __syncthreads();

    dw_half(0);
    __syncthreads();
    pw_half(0);
    __syncthreads();          // WAR: dy reused by half 1
    dw_half(1);
    __syncthreads();
    pw_half(1);
}

extern "C" void kernel_launch(void* const* d_in, const int* in_sizes, int n_in,
                              void* d_out, int out_size)
{
    const float* x     = (const float*)d_in[0];
    const float* dwk   = (const float*)d_in[1];
    const float* pwk   = (const float*)d_in[2];
    const float* gam   = (const float*)d_in[3];
    const float* bet   = (const float*)d_in[4];
    const float* mmean = (const float*)d_in[5];
    const float* mvar  = (const float*)d_in[6];
    float* out = (float*)d_out;

    cudaFuncSetAttribute(fused_gconv_kernel,
                         cudaFuncAttributeMaxDynamicSharedMemorySize, SMEM_BYTES);

    dim3 grid(Gn, (Hn / HT) * (Wn / WT), Bn);   // 32 x 16 x 16 = 8192 blocks
    fused_gconv_kernel<<<grid, 256, SMEM_BYTES>>>(x, dwk, pwk, gam, bet, mmean, mvar, out);
}